// round 2
// baseline (speedup 1.0000x reference)
#include <cuda_runtime.h>
#include <math.h>

#define NN 100000
#define D  128

// Scratch (device globals — no allocations allowed)
__device__ float g_agg[(size_t)NN * D];
__device__ float g_h1[(size_t)NN * D];
__device__ float g_h2[(size_t)NN * D];
__device__ float g_deg[NN];
__device__ float g_s[NN];
__device__ float g_z[NN];
__device__ float g_aggs[NN];

// ---------------------------------------------------------------------------
// degree: deg[dst] += 1 over all edges
// ---------------------------------------------------------------------------
__global__ void deg_kernel(const int* __restrict__ dst, int E) {
    int i = blockIdx.x * blockDim.x + threadIdx.x;
    int stride = gridDim.x * blockDim.x;
    for (; i < E; i += stride)
        atomicAdd(&g_deg[dst[i]], 1.0f);
}

// ---------------------------------------------------------------------------
// scatter128: agg[dst] += h[src]  (128 floats/edge; warp per edge)
// ---------------------------------------------------------------------------
__global__ void scatter128(const float* __restrict__ h,
                           const int* __restrict__ src,
                           const int* __restrict__ dst, int E) {
    int lane = threadIdx.x & 31;
    int warp = (blockIdx.x * blockDim.x + threadIdx.x) >> 5;
    int nwarps = (gridDim.x * blockDim.x) >> 5;
    for (int e = warp; e < E; e += nwarps) {
        int s = __ldg(src + e);
        int d = __ldg(dst + e);
        float4 v = __ldg(((const float4*)(h + (size_t)s * D)) + lane);
        float* p = g_agg + (size_t)d * D + lane * 4;
        asm volatile("red.global.add.v4.f32 [%0], {%1,%2,%3,%4};"
                     :: "l"(p), "f"(v.x), "f"(v.y), "f"(v.z), "f"(v.w)
                     : "memory");
    }
}

// ---------------------------------------------------------------------------
// Fused layer body: out[n,:] = relu( (g_agg[n,:]/max(deg,1)) @ Wl^T + bl
//                                    + h[n,:] @ Wr^T )
// Weights (transposed) in smem; 128 rows per block; 2 rows per warp per iter.
// ---------------------------------------------------------------------------
__global__ __launch_bounds__(256) void gemm_combine(
    const float* __restrict__ h,
    const float* __restrict__ Wl, const float* __restrict__ bl,
    const float* __restrict__ Wr,
    float* __restrict__ out, int n_rows, int do_relu)
{
    extern __shared__ float sm[];
    float* sWl   = sm;                 // [128][128] transposed: sWl[k*128+o]
    float* sWr   = sm + 16384;
    float* sB    = sm + 32768;         // [128]
    float* sRows = sm + 32768 + 128;   // [8 warps][4 rows][128]

    int tid = threadIdx.x;
    for (int i = tid; i < 16384; i += 256) {
        int o = i >> 7, k = i & 127;
        sWl[k * 128 + o] = Wl[i];
        sWr[k * 128 + o] = Wr[i];
    }
    if (tid < 128) sB[tid] = bl[tid];
    __syncthreads();

    int warp = tid >> 5, lane = tid & 31;
    int row_base = blockIdx.x * 128 + warp * 16;
    float* myRows = sRows + warp * 4 * 128;
    const float4 z4 = make_float4(0.f, 0.f, 0.f, 0.f);

    for (int it = 0; it < 8; ++it) {
        int r0 = row_base + it * 2;
        int r1 = r0 + 1;
        bool v0 = r0 < n_rows, v1 = r1 < n_rows;

        float4 a0 = v0 ? __ldg(((const float4*)(g_agg + (size_t)r0 * D)) + lane) : z4;
        float4 x0 = v0 ? __ldg(((const float4*)(h     + (size_t)r0 * D)) + lane) : z4;
        float4 a1 = v1 ? __ldg(((const float4*)(g_agg + (size_t)r1 * D)) + lane) : z4;
        float4 x1 = v1 ? __ldg(((const float4*)(h     + (size_t)r1 * D)) + lane) : z4;
        __syncwarp();
        ((float4*)(myRows      ))[lane] = a0;
        ((float4*)(myRows + 128))[lane] = x0;
        ((float4*)(myRows + 256))[lane] = a1;
        ((float4*)(myRows + 384))[lane] = x1;
        __syncwarp();

        float4 accA0 = z4, accB0 = z4, accA1 = z4, accB1 = z4;
        #pragma unroll 16
        for (int k = 0; k < 128; ++k) {
            float4 wl = ((const float4*)(sWl + k * 128))[lane];
            float4 wr = ((const float4*)(sWr + k * 128))[lane];
            float p0 = myRows[k];
            float q0 = myRows[128 + k];
            float p1 = myRows[256 + k];
            float q1 = myRows[384 + k];
            accA0.x = fmaf(p0, wl.x, accA0.x); accA0.y = fmaf(p0, wl.y, accA0.y);
            accA0.z = fmaf(p0, wl.z, accA0.z); accA0.w = fmaf(p0, wl.w, accA0.w);
            accB0.x = fmaf(q0, wr.x, accB0.x); accB0.y = fmaf(q0, wr.y, accB0.y);
            accB0.z = fmaf(q0, wr.z, accB0.z); accB0.w = fmaf(q0, wr.w, accB0.w);
            accA1.x = fmaf(p1, wl.x, accA1.x); accA1.y = fmaf(p1, wl.y, accA1.y);
            accA1.z = fmaf(p1, wl.z, accA1.z); accA1.w = fmaf(p1, wl.w, accA1.w);
            accB1.x = fmaf(q1, wr.x, accB1.x); accB1.y = fmaf(q1, wr.y, accB1.y);
            accB1.z = fmaf(q1, wr.z, accB1.z); accB1.w = fmaf(q1, wr.w, accB1.w);
        }

        float4 b = ((const float4*)sB)[lane];
        if (v0) {
            float id = 1.0f / fmaxf(g_deg[r0], 1.0f);
            float4 o4;
            o4.x = fmaf(accA0.x, id, accB0.x + b.x);
            o4.y = fmaf(accA0.y, id, accB0.y + b.y);
            o4.z = fmaf(accA0.z, id, accB0.z + b.z);
            o4.w = fmaf(accA0.w, id, accB0.w + b.w);
            if (do_relu) {
                o4.x = fmaxf(o4.x, 0.f); o4.y = fmaxf(o4.y, 0.f);
                o4.z = fmaxf(o4.z, 0.f); o4.w = fmaxf(o4.w, 0.f);
            }
            ((float4*)(out + (size_t)r0 * D))[lane] = o4;
        }
        if (v1) {
            float id = 1.0f / fmaxf(g_deg[r1], 1.0f);
            float4 o4;
            o4.x = fmaf(accA1.x, id, accB1.x + b.x);
            o4.y = fmaf(accA1.y, id, accB1.y + b.y);
            o4.z = fmaf(accA1.z, id, accB1.z + b.z);
            o4.w = fmaf(accA1.w, id, accB1.w + b.w);
            if (do_relu) {
                o4.x = fmaxf(o4.x, 0.f); o4.y = fmaxf(o4.y, 0.f);
                o4.z = fmaxf(o4.z, 0.f); o4.w = fmaxf(o4.w, 0.f);
            }
            ((float4*)(out + (size_t)r1 * D))[lane] = o4;
        }
        __syncwarp();
    }
}

// ---------------------------------------------------------------------------
// Layer 2 (DOUT=1): scalarize BEFORE aggregation (aggregation is linear):
//   s[n] = h2[n]·Wl2 ; z[n] = h2[n]·Wr2       (warp per node)
// ---------------------------------------------------------------------------
__global__ void dot2_kernel(const float* __restrict__ h2,
                            const float* __restrict__ Wl2,
                            const float* __restrict__ Wr2, int n) {
    int lane = threadIdx.x & 31;
    int warp = (blockIdx.x * blockDim.x + threadIdx.x) >> 5;
    int nwarps = (gridDim.x * blockDim.x) >> 5;
    float4 wl = __ldg(((const float4*)Wl2) + lane);
    float4 wr = __ldg(((const float4*)Wr2) + lane);
    for (int r = warp; r < n; r += nwarps) {
        float4 hv = __ldg(((const float4*)(h2 + (size_t)r * D)) + lane);
        float ds = hv.x * wl.x + hv.y * wl.y + hv.z * wl.z + hv.w * wl.w;
        float dz = hv.x * wr.x + hv.y * wr.y + hv.z * wr.z + hv.w * wr.w;
        #pragma unroll
        for (int off = 16; off > 0; off >>= 1) {
            ds += __shfl_down_sync(0xffffffffu, ds, off);
            dz += __shfl_down_sync(0xffffffffu, dz, off);
        }
        if (lane == 0) { g_s[r] = ds; g_z[r] = dz; }
    }
}

__global__ void scatter_scalar(const int* __restrict__ src,
                               const int* __restrict__ dst, int E) {
    int i = blockIdx.x * blockDim.x + threadIdx.x;
    int stride = gridDim.x * blockDim.x;
    for (; i < E; i += stride)
        atomicAdd(&g_aggs[dst[i]], g_s[src[i]]);
}

__global__ void final_kernel(const float* __restrict__ bl2,
                             float* __restrict__ out, int n) {
    int i = blockIdx.x * blockDim.x + threadIdx.x;
    if (i >= n) return;
    float v = g_aggs[i] / fmaxf(g_deg[i], 1.0f) + bl2[0] + g_z[i];
    out[i]     = v;
    out[n + i] = 1.0f / (1.0f + expf(-v));
}

// ---------------------------------------------------------------------------
extern "C" void kernel_launch(void* const* d_in, const int* in_sizes, int n_in,
                              void* d_out, int out_size) {
    const float* x   = (const float*)d_in[0];
    const int*   ei  = (const int*)d_in[1];
    const float* Wl0 = (const float*)d_in[2];
    const float* bl0 = (const float*)d_in[3];
    const float* Wr0 = (const float*)d_in[4];
    const float* Wl1 = (const float*)d_in[5];
    const float* bl1 = (const float*)d_in[6];
    const float* Wr1 = (const float*)d_in[7];
    const float* Wl2 = (const float*)d_in[8];
    const float* bl2 = (const float*)d_in[9];
    const float* Wr2 = (const float*)d_in[10];
    float* out = (float*)d_out;

    int n = in_sizes[0] / D;      // 100000
    int E = in_sizes[1] / 2;      // 1600000
    const int* src = ei;
    const int* dst = ei + E;

    void *p_agg, *p_deg, *p_aggs;
    cudaGetSymbolAddress(&p_agg, g_agg);
    cudaGetSymbolAddress(&p_deg, g_deg);
    cudaGetSymbolAddress(&p_aggs, g_aggs);

    const int SMEM = (16384 * 2 + 128 + 8 * 4 * 128) * sizeof(float); // 147968
    cudaFuncSetAttribute(gemm_combine, cudaFuncAttributeMaxDynamicSharedMemorySize, SMEM);

    float *h1, *h2;
    cudaGetSymbolAddress((void**)&h1, g_h1);
    cudaGetSymbolAddress((void**)&h2, g_h2);

    int gemm_blocks = (n + 127) / 128;

    // degree (shared by all layers) + zero agg
    cudaMemsetAsync(p_deg, 0, (size_t)n * sizeof(float));
    cudaMemsetAsync(p_agg, 0, (size_t)n * D * sizeof(float));
    deg_kernel<<<6250, 256>>>(dst, E);

    // Layer 0
    scatter128<<<8192, 256>>>(x, src, dst, E);
    gemm_combine<<<gemm_blocks, 256, SMEM>>>(x, Wl0, bl0, Wr0, h1, n, 1);

    // Layer 1
    cudaMemsetAsync(p_agg, 0, (size_t)n * D * sizeof(float));
    scatter128<<<8192, 256>>>(h1, src, dst, E);
    gemm_combine<<<gemm_blocks, 256, SMEM>>>(h1, Wl1, bl1, Wr1, h2, n, 1);

    // Layer 2 (scalarized: project to 1-d BEFORE the edge scatter)
    dot2_kernel<<<12500, 256>>>(h2, Wl2, Wr2, n);
    cudaMemsetAsync(p_aggs, 0, (size_t)n * sizeof(float));
    scatter_scalar<<<6250, 256>>>(src, dst, E);
    final_kernel<<<(n + 255) / 256, 256>>>(bl2, out, n);
}

// round 3
// speedup vs baseline: 2.0534x; 2.0534x over previous
#include <cuda_runtime.h>
#include <cuda_bf16.h>
#include <math.h>

#define NN 100000
#define EE 1600000
#define D  128

// ---------------- device scratch (no allocations allowed) -------------------
__device__ __align__(16) float g_h1[(size_t)NN * D];
__device__ __align__(16) float g_h2[(size_t)NN * D];
__device__ __align__(16) __nv_bfloat16 g_ahi[(size_t)NN * D];  // agg hi
__device__ __align__(16) __nv_bfloat16 g_alo[(size_t)NN * D];  // agg lo
__device__ __align__(16) __nv_bfloat16 g_fhi[(size_t)NN * D];  // feat hi (x -> h1)
__device__ __align__(16) __nv_bfloat16 g_flo[(size_t)NN * D];  // feat lo
__device__ __align__(16) __nv_bfloat16 g_whi[128 * 256];       // [Wl;Wr] hi, [n][k]
__device__ __align__(16) __nv_bfloat16 g_wlo[128 * 256];
__device__ int g_cnt[NN];
__device__ int g_off[NN + 1];
__device__ int g_cur[NN];
__device__ int g_csr[EE];
__device__ float g_s[NN];
__device__ float g_z[NN];

// ---------------------------------------------------------------------------
__device__ __forceinline__ void split2(float a, float b,
                                       unsigned& hi, unsigned& lo) {
    __nv_bfloat16 ha = __float2bfloat16_rn(a);
    __nv_bfloat16 hb = __float2bfloat16_rn(b);
    __nv_bfloat16 la = __float2bfloat16_rn(a - __bfloat162float(ha));
    __nv_bfloat16 lb = __float2bfloat16_rn(b - __bfloat162float(hb));
    __nv_bfloat162 H = __nv_bfloat162(ha, hb);
    __nv_bfloat162 L = __nv_bfloat162(la, lb);
    hi = *(unsigned*)&H;
    lo = *(unsigned*)&L;
}

// ---------------- CSR build --------------------------------------------------
__global__ void count_kernel(const int* __restrict__ dst, int E) {
    int i = blockIdx.x * blockDim.x + threadIdx.x;
    int stride = gridDim.x * blockDim.x;
    for (; i < E; i += stride) atomicAdd(&g_cnt[dst[i]], 1);
}

__global__ void scan_kernel(int n) {   // single block, 1024 threads
    __shared__ int ssum[1024];
    int tid = threadIdx.x;
    int chunk = (n + 1023) / 1024;
    int lo = tid * chunk;
    int hi = min(lo + chunk, n);
    int s = 0;
    for (int j = lo; j < hi; ++j) s += g_cnt[j];
    ssum[tid] = s;
    __syncthreads();
    // inclusive Hillis-Steele
    for (int off = 1; off < 1024; off <<= 1) {
        int v = (tid >= off) ? ssum[tid - off] : 0;
        __syncthreads();
        ssum[tid] += v;
        __syncthreads();
    }
    int run = ssum[tid] - s;  // exclusive prefix for this thread's chunk
    for (int j = lo; j < hi; ++j) {
        g_off[j] = run;
        g_cur[j] = run;
        run += g_cnt[j];
    }
    if (lo < n && hi == n) g_off[n] = run;
}

__global__ void fill_kernel(const int* __restrict__ src,
                            const int* __restrict__ dst, int E) {
    int i = blockIdx.x * blockDim.x + threadIdx.x;
    int stride = gridDim.x * blockDim.x;
    for (; i < E; i += stride) {
        int pos = atomicAdd(&g_cur[dst[i]], 1);
        g_csr[pos] = src[i];
    }
}

// ---------------- mean gather (atomic-free), emits bf16 hi/lo ---------------
__global__ void gather_mean(const float* __restrict__ h, int n) {
    int lane = threadIdx.x & 31;
    int w = (blockIdx.x * blockDim.x + threadIdx.x) >> 5;
    int nw = (gridDim.x * blockDim.x) >> 5;
    for (int i = w; i < n; i += nw) {
        int beg = g_off[i], end = g_off[i + 1];
        float4 acc = make_float4(0.f, 0.f, 0.f, 0.f);
        for (int e = beg; e < end; ++e) {
            int s = g_csr[e];
            float4 v = __ldg(((const float4*)(h + (size_t)s * D)) + lane);
            acc.x += v.x; acc.y += v.y; acc.z += v.z; acc.w += v.w;
        }
        float inv = 1.0f / fmaxf((float)(end - beg), 1.0f);
        acc.x *= inv; acc.y *= inv; acc.z *= inv; acc.w *= inv;
        unsigned h01, l01, h23, l23;
        split2(acc.x, acc.y, h01, l01);
        split2(acc.z, acc.w, h23, l23);
        uint2 H = make_uint2(h01, h23);
        uint2 L = make_uint2(l01, l23);
        *((uint2*)(g_ahi + (size_t)i * D + lane * 4)) = H;
        *((uint2*)(g_alo + (size_t)i * D + lane * 4)) = L;
    }
}

// ---------------- converters -------------------------------------------------
__global__ void convert_x(const float* __restrict__ x, int n4) {
    int i = blockIdx.x * blockDim.x + threadIdx.x;
    if (i >= n4) return;
    float4 v = __ldg(((const float4*)x) + i);
    unsigned h01, l01, h23, l23;
    split2(v.x, v.y, h01, l01);
    split2(v.z, v.w, h23, l23);
    *((uint2*)(g_fhi + (size_t)i * 4)) = make_uint2(h01, h23);
    *((uint2*)(g_flo + (size_t)i * 4)) = make_uint2(l01, l23);
}

__global__ void prep_w(const float* __restrict__ Wl, const float* __restrict__ Wr) {
    int i = blockIdx.x * blockDim.x + threadIdx.x;  // 0..32767
    int nrow = i >> 8, k = i & 255;
    float w = (k < 128) ? Wl[nrow * 128 + k] : Wr[nrow * 128 + (k - 128)];
    __nv_bfloat16 h = __float2bfloat16_rn(w);
    __nv_bfloat16 l = __float2bfloat16_rn(w - __bfloat162float(h));
    g_whi[nrow * 256 + k] = h;
    g_wlo[nrow * 256 + k] = l;
}

// ---------------- tensor-core GEMM ------------------------------------------
// out[m][n] = relu( sum_k A[m][k] * W[n][k] + bias[n] ),  K = 256
// A = [agg(/deg) | feat],  bf16 hi/lo split, 3 MMAs per (hi,lo) pair.
// Block: 128 rows x 128 cols. 512 threads = 16 warps (8 m-slots x 2 n-halves).
#define SM_BH 0
#define SM_BL 67584
#define SM_AB 135168
#define SMEM_TOTAL (135168 + 73728)
#define ABUF_HALF 18432   // halves per A buffer (hi 9216 + lo 9216)

__device__ __forceinline__ unsigned su32(const void* p) {
    return (unsigned)__cvta_generic_to_shared(p);
}
__device__ __forceinline__ void cpa16(unsigned dst, const void* src, bool ok) {
    asm volatile("cp.async.cg.shared.global [%0], [%1], 16, %2;"
                 :: "r"(dst), "l"(src), "r"(ok ? 16 : 0));
}
__device__ __forceinline__ void mma_bf16(float* d, const unsigned* a,
                                         unsigned b0, unsigned b1) {
    asm volatile(
        "mma.sync.aligned.m16n8k16.row.col.f32.bf16.bf16.f32 "
        "{%0,%1,%2,%3}, {%4,%5,%6,%7}, {%8,%9}, {%0,%1,%2,%3};"
        : "+f"(d[0]), "+f"(d[1]), "+f"(d[2]), "+f"(d[3])
        : "r"(a[0]), "r"(a[1]), "r"(a[2]), "r"(a[3]), "r"(b0), "r"(b1));
}

__global__ __launch_bounds__(512) void gemm_mma(
    const __nv_bfloat16* __restrict__ aggHi, const __nv_bfloat16* __restrict__ aggLo,
    const __nv_bfloat16* __restrict__ featHi, const __nv_bfloat16* __restrict__ featLo,
    const float* __restrict__ bias,
    float* __restrict__ outF,
    __nv_bfloat16* __restrict__ outHi, __nv_bfloat16* __restrict__ outLo,
    int n, int do_hilo)
{
    extern __shared__ char sm[];
    __nv_bfloat16* Bh = (__nv_bfloat16*)(sm + SM_BH);   // [128][264]
    __nv_bfloat16* Bl = (__nv_bfloat16*)(sm + SM_BL);   // [128][264]
    __nv_bfloat16* Ab = (__nv_bfloat16*)(sm + SM_AB);   // 2 x (hi[128][72], lo[128][72])

    int tid = threadIdx.x;
    int lane = tid & 31;
    int wid = tid >> 5;
    int mwarp = wid & 7;          // 8 m-slots of 16 rows
    int nwarp = wid >> 3;         // 2 n-halves of 64 cols
    int g = lane >> 2, t = lane & 3;

    // --- load B (weights hi/lo) into smem ---
    for (int u = tid; u < 4096; u += 512) {
        int nrow = u >> 5, seg = u & 31;
        cpa16(su32(Bh + nrow * 264) + seg * 16, g_whi + nrow * 256 + seg * 8, true);
        cpa16(su32(Bl + nrow * 264) + seg * 16, g_wlo + nrow * 256 + seg * 8, true);
    }

    // --- A chunk loader: chunk c covers k [c*64, c*64+64) ---
    auto loadA = [&](int c, int buf) {
        const __nv_bfloat16* sH = (c < 2) ? aggHi : featHi;
        const __nv_bfloat16* sL = (c < 2) ? aggLo : featLo;
        int koff = (c & 1) * 64;
        __nv_bfloat16* dH = Ab + buf * ABUF_HALF;
        __nv_bfloat16* dL = dH + 9216;
        #pragma unroll
        for (int u = tid; u < 1024; u += 512) {
            int r = u >> 3, seg = u & 7;
            int row = blockIdx.x * 128 + r;
            bool ok = row < n;
            int rr = ok ? row : 0;
            cpa16(su32(dH + r * 72) + seg * 16,
                  sH + (size_t)rr * 128 + koff + seg * 8, ok);
            cpa16(su32(dL + r * 72) + seg * 16,
                  sL + (size_t)rr * 128 + koff + seg * 8, ok);
        }
    };

    loadA(0, 0);
    asm volatile("cp.async.commit_group;");   // group: B + A0
    loadA(1, 1);
    asm volatile("cp.async.commit_group;");   // group: A1
    asm volatile("cp.async.wait_group 1;");   // B + A0 done
    __syncthreads();

    float acc[8][4];
    #pragma unroll
    for (int i = 0; i < 8; ++i)
        #pragma unroll
        for (int j = 0; j < 4; ++j) acc[i][j] = 0.f;

    for (int c = 0; c < 4; ++c) {
        const __nv_bfloat16* Ah = Ab + (c & 1) * ABUF_HALF;
        const __nv_bfloat16* Al = Ah + 9216;
        #pragma unroll
        for (int ks = 0; ks < 4; ++ks) {
            int k = ks * 16;
            const __nv_bfloat16* pa = Ah + (mwarp * 16 + g) * 72 + t * 2 + k;
            const __nv_bfloat16* pl = Al + (mwarp * 16 + g) * 72 + t * 2 + k;
            unsigned ah[4], al[4];
            ah[0] = *(const unsigned*)(pa);
            ah[1] = *(const unsigned*)(pa + 8 * 72);
            ah[2] = *(const unsigned*)(pa + 8);
            ah[3] = *(const unsigned*)(pa + 8 * 72 + 8);
            al[0] = *(const unsigned*)(pl);
            al[1] = *(const unsigned*)(pl + 8 * 72);
            al[2] = *(const unsigned*)(pl + 8);
            al[3] = *(const unsigned*)(pl + 8 * 72 + 8);
            #pragma unroll
            for (int nt = 0; nt < 8; ++nt) {
                int nn = nwarp * 64 + nt * 8 + g;
                int kk = c * 64 + k + t * 2;
                unsigned b0h = *(const unsigned*)(Bh + nn * 264 + kk);
                unsigned b1h = *(const unsigned*)(Bh + nn * 264 + kk + 8);
                unsigned b0l = *(const unsigned*)(Bl + nn * 264 + kk);
                unsigned b1l = *(const unsigned*)(Bl + nn * 264 + kk + 8);
                mma_bf16(acc[nt], ah, b0h, b1h);
                mma_bf16(acc[nt], ah, b0l, b1l);
                mma_bf16(acc[nt], al, b0h, b1h);
            }
        }
        __syncthreads();            // everyone done with buf (c&1)
        if (c + 2 < 4) loadA(c + 2, c & 1);
        asm volatile("cp.async.commit_group;");
        asm volatile("cp.async.wait_group 1;");
        __syncthreads();
    }

    // --- epilogue: bias + relu; write fp32 (+ bf16 hi/lo) ---
    int row0 = blockIdx.x * 128 + mwarp * 16 + g;
    int row1 = row0 + 8;
    #pragma unroll
    for (int nt = 0; nt < 8; ++nt) {
        int col = nwarp * 64 + nt * 8 + t * 2;
        float b0 = __ldg(bias + col), b1 = __ldg(bias + col + 1);
        float v0 = fmaxf(acc[nt][0] + b0, 0.f);
        float v1 = fmaxf(acc[nt][1] + b1, 0.f);
        float v2 = fmaxf(acc[nt][2] + b0, 0.f);
        float v3 = fmaxf(acc[nt][3] + b1, 0.f);
        if (row0 < n) {
            *((float2*)(outF + (size_t)row0 * D + col)) = make_float2(v0, v1);
            if (do_hilo) {
                unsigned h01, l01;
                split2(v0, v1, h01, l01);
                *((unsigned*)(outHi + (size_t)row0 * D + col)) = h01;
                *((unsigned*)(outLo + (size_t)row0 * D + col)) = l01;
            }
        }
        if (row1 < n) {
            *((float2*)(outF + (size_t)row1 * D + col)) = make_float2(v2, v3);
            if (do_hilo) {
                unsigned h23, l23;
                split2(v2, v3, h23, l23);
                *((unsigned*)(outHi + (size_t)row1 * D + col)) = h23;
                *((unsigned*)(outLo + (size_t)row1 * D + col)) = l23;
            }
        }
    }
}

// ---------------- layer 2 (DOUT=1): scalarize before aggregation ------------
__global__ void dot2_kernel(const float* __restrict__ h2,
                            const float* __restrict__ Wl2,
                            const float* __restrict__ Wr2, int n) {
    int lane = threadIdx.x & 31;
    int warp = (blockIdx.x * blockDim.x + threadIdx.x) >> 5;
    int nwarps = (gridDim.x * blockDim.x) >> 5;
    float4 wl = __ldg(((const float4*)Wl2) + lane);
    float4 wr = __ldg(((const float4*)Wr2) + lane);
    for (int r = warp; r < n; r += nwarps) {
        float4 hv = __ldg(((const float4*)(h2 + (size_t)r * D)) + lane);
        float ds = hv.x * wl.x + hv.y * wl.y + hv.z * wl.z + hv.w * wl.w;
        float dz = hv.x * wr.x + hv.y * wr.y + hv.z * wr.z + hv.w * wr.w;
        #pragma unroll
        for (int off = 16; off > 0; off >>= 1) {
            ds += __shfl_down_sync(0xffffffffu, ds, off);
            dz += __shfl_down_sync(0xffffffffu, dz, off);
        }
        if (lane == 0) { g_s[r] = ds; g_z[r] = dz; }
    }
}

__global__ void final_fused(const float* __restrict__ bl2,
                            float* __restrict__ out, int n) {
    int i = blockIdx.x * blockDim.x + threadIdx.x;
    if (i >= n) return;
    int beg = g_off[i], end = g_off[i + 1];
    float acc = 0.f;
    for (int e = beg; e < end; ++e) acc += g_s[g_csr[e]];
    float v = acc / fmaxf((float)(end - beg), 1.0f) + __ldg(bl2) + g_z[i];
    out[i] = v;
    out[n + i] = 1.0f / (1.0f + expf(-v));
}

// ---------------------------------------------------------------------------
extern "C" void kernel_launch(void* const* d_in, const int* in_sizes, int n_in,
                              void* d_out, int out_size) {
    const float* x   = (const float*)d_in[0];
    const int*   ei  = (const int*)d_in[1];
    const float* Wl0 = (const float*)d_in[2];
    const float* bl0 = (const float*)d_in[3];
    const float* Wr0 = (const float*)d_in[4];
    const float* Wl1 = (const float*)d_in[5];
    const float* bl1 = (const float*)d_in[6];
    const float* Wr1 = (const float*)d_in[7];
    const float* Wl2 = (const float*)d_in[8];
    const float* bl2 = (const float*)d_in[9];
    const float* Wr2 = (const float*)d_in[10];
    float* out = (float*)d_out;

    int n = in_sizes[0] / D;   // 100000
    int E = in_sizes[1] / 2;   // 1600000
    const int* src = ei;
    const int* dst = ei + E;

    void* p_cnt;
    cudaGetSymbolAddress(&p_cnt, g_cnt);
    float *h1, *h2;
    cudaGetSymbolAddress((void**)&h1, g_h1);
    cudaGetSymbolAddress((void**)&h2, g_h2);
    __nv_bfloat16 *ahi, *alo, *fhi, *flo;
    cudaGetSymbolAddress((void**)&ahi, g_ahi);
    cudaGetSymbolAddress((void**)&alo, g_alo);
    cudaGetSymbolAddress((void**)&fhi, g_fhi);
    cudaGetSymbolAddress((void**)&flo, g_flo);

    cudaFuncSetAttribute(gemm_mma, cudaFuncAttributeMaxDynamicSharedMemorySize,
                         SMEM_TOTAL);

    int gemm_blocks = (n + 127) / 128;   // 782

    // CSR build
    cudaMemsetAsync(p_cnt, 0, (size_t)n * sizeof(int));
    count_kernel<<<6250, 256>>>(dst, E);
    scan_kernel<<<1, 1024>>>(n);
    fill_kernel<<<6250, 256>>>(src, dst, E);

    // Layer 0
    convert_x<<<(n * 32 + 255) / 256, 256>>>(x, n * 32);  // n*128/4 float4s
    gather_mean<<<12500, 256>>>(x, n);
    prep_w<<<128, 256>>>(Wl0, Wr0);
    gemm_mma<<<gemm_blocks, 512, SMEM_TOTAL>>>(ahi, alo, fhi, flo, bl0,
                                               h1, fhi, flo, n, 1);

    // Layer 1
    gather_mean<<<12500, 256>>>(h1, n);
    prep_w<<<128, 256>>>(Wl1, Wr1);
    gemm_mma<<<gemm_blocks, 512, SMEM_TOTAL>>>(ahi, alo, fhi, flo, bl1,
                                               h2, (__nv_bfloat16*)0,
                                               (__nv_bfloat16*)0, n, 0);

    // Layer 2 (scalarized before aggregation) + output
    dot2_kernel<<<12500, 256>>>(h2, Wl2, Wr2, n);
    final_fused<<<(n + 255) / 256, 256>>>(bl2, out, n);
}

// round 4
// speedup vs baseline: 3.2252x; 1.5707x over previous
#include <cuda_runtime.h>
#include <cuda_bf16.h>
#include <cuda_fp16.h>
#include <math.h>

#define NN 100000
#define EE 1600000
#define D  128

// ---------------- device scratch (no allocations allowed) -------------------
__device__ __align__(16) __nv_bfloat16 g_ahi[(size_t)NN * D];  // agg hi
__device__ __align__(16) __nv_bfloat16 g_alo[(size_t)NN * D];  // agg lo
__device__ __align__(16) __nv_bfloat16 g_fhi[(size_t)NN * D];  // feat hi
__device__ __align__(16) __nv_bfloat16 g_flo[(size_t)NN * D];  // feat lo
__device__ __align__(16) __half        g_f16[(size_t)NN * D];  // feat fp16 (gather src)
__device__ __align__(16) __nv_bfloat16 g_whi[128 * 256];       // [Wl;Wr] hi, [n][k]
__device__ __align__(16) __nv_bfloat16 g_wlo[128 * 256];
__device__ int g_cnt[NN];
__device__ int g_pre[NN];
__device__ int g_bsum[128];
__device__ int g_off[NN + 1];
__device__ int g_cur[NN];
__device__ int g_csr[EE];
__device__ float g_s[NN];
__device__ float g_z[NN];

// ---------------------------------------------------------------------------
__device__ __forceinline__ void split2(float a, float b,
                                       unsigned& hi, unsigned& lo) {
    __nv_bfloat16 ha = __float2bfloat16_rn(a);
    __nv_bfloat16 hb = __float2bfloat16_rn(b);
    __nv_bfloat16 la = __float2bfloat16_rn(a - __bfloat162float(ha));
    __nv_bfloat16 lb = __float2bfloat16_rn(b - __bfloat162float(hb));
    __nv_bfloat162 H = __nv_bfloat162(ha, hb);
    __nv_bfloat162 L = __nv_bfloat162(la, lb);
    hi = *(unsigned*)&H;
    lo = *(unsigned*)&L;
}

// ---------------- CSR build --------------------------------------------------
__global__ void count_kernel(const int* __restrict__ dst, int E) {
    int i = blockIdx.x * blockDim.x + threadIdx.x;
    int stride = gridDim.x * blockDim.x;
    for (; i < E; i += stride) atomicAdd(&g_cnt[dst[i]], 1);
}

__global__ void scan1(int n) {       // grid 98 x 1024
    __shared__ int s[1024];
    int tid = threadIdx.x;
    int i = blockIdx.x * 1024 + tid;
    int v = (i < n) ? g_cnt[i] : 0;
    s[tid] = v;
    __syncthreads();
    for (int off = 1; off < 1024; off <<= 1) {
        int t = (tid >= off) ? s[tid - off] : 0;
        __syncthreads();
        s[tid] += t;
        __syncthreads();
    }
    if (i < n) g_pre[i] = s[tid] - v;        // exclusive within block
    if (tid == 1023) g_bsum[blockIdx.x] = s[1023];
}

__global__ void scan2(int nb) {      // 1 block x 128
    __shared__ int s[128];
    int tid = threadIdx.x;
    int v = (tid < nb) ? g_bsum[tid] : 0;
    s[tid] = v;
    __syncthreads();
    for (int off = 1; off < 128; off <<= 1) {
        int t = (tid >= off) ? s[tid - off] : 0;
        __syncthreads();
        s[tid] += t;
        __syncthreads();
    }
    if (tid < nb) g_bsum[tid] = s[tid] - v;  // exclusive block offsets
}

__global__ void scan3(int n, int E) {
    int i = blockIdx.x * 1024 + threadIdx.x;
    if (i < n) {
        int o = g_pre[i] + g_bsum[blockIdx.x];
        g_off[i] = o;
        g_cur[i] = o;
    }
    if (i == 0) g_off[n] = E;
}

__global__ void fill_kernel(const int* __restrict__ src,
                            const int* __restrict__ dst, int E) {
    int i = blockIdx.x * blockDim.x + threadIdx.x;
    int stride = gridDim.x * blockDim.x;
    for (; i < E; i += stride) {
        int pos = atomicAdd(&g_cur[dst[i]], 1);
        g_csr[pos] = src[i];
    }
}

// ---------------- mean gather (fp16 rows, atomic-free), emits bf16 hi/lo ----
__global__ void gather_mean(const __half* __restrict__ h, int n) {
    int lane = threadIdx.x & 31;
    int w = (blockIdx.x * blockDim.x + threadIdx.x) >> 5;
    int nw = (gridDim.x * blockDim.x) >> 5;
    for (int i = w; i < n; i += nw) {
        int beg = g_off[i], end = g_off[i + 1];
        float4 acc = make_float4(0.f, 0.f, 0.f, 0.f);
        for (int e = beg; e < end; ++e) {
            int s = g_csr[e];
            uint2 raw = __ldg(((const uint2*)(h + (size_t)s * D)) + lane);
            __half2* p = (__half2*)&raw;
            float2 f01 = __half22float2(p[0]);
            float2 f23 = __half22float2(p[1]);
            acc.x += f01.x; acc.y += f01.y; acc.z += f23.x; acc.w += f23.y;
        }
        float inv = 1.0f / fmaxf((float)(end - beg), 1.0f);
        acc.x *= inv; acc.y *= inv; acc.z *= inv; acc.w *= inv;
        unsigned h01, l01, h23, l23;
        split2(acc.x, acc.y, h01, l01);
        split2(acc.z, acc.w, h23, l23);
        *((uint2*)(g_ahi + (size_t)i * D + lane * 4)) = make_uint2(h01, h23);
        *((uint2*)(g_alo + (size_t)i * D + lane * 4)) = make_uint2(l01, l23);
    }
}

// ---------------- converters -------------------------------------------------
__global__ void convert_x(const float* __restrict__ x, int n4) {
    int i = blockIdx.x * blockDim.x + threadIdx.x;
    if (i >= n4) return;
    float4 v = __ldg(((const float4*)x) + i);
    unsigned h01, l01, h23, l23;
    split2(v.x, v.y, h01, l01);
    split2(v.z, v.w, h23, l23);
    *((uint2*)(g_fhi + (size_t)i * 4)) = make_uint2(h01, h23);
    *((uint2*)(g_flo + (size_t)i * 4)) = make_uint2(l01, l23);
    __half2 a = __floats2half2_rn(v.x, v.y);
    __half2 b = __floats2half2_rn(v.z, v.w);
    uint2 F;
    F.x = *(unsigned*)&a;
    F.y = *(unsigned*)&b;
    *((uint2*)(g_f16 + (size_t)i * 4)) = F;
}

__global__ void prep_w(const float* __restrict__ Wl, const float* __restrict__ Wr) {
    int i = blockIdx.x * blockDim.x + threadIdx.x;  // 0..32767
    int nrow = i >> 8, k = i & 255;
    float w = (k < 128) ? Wl[nrow * 128 + k] : Wr[nrow * 128 + (k - 128)];
    __nv_bfloat16 h = __float2bfloat16_rn(w);
    __nv_bfloat16 l = __float2bfloat16_rn(w - __bfloat162float(h));
    g_whi[nrow * 256 + k] = h;
    g_wlo[nrow * 256 + k] = l;
}

// ---------------- tensor-core GEMM ------------------------------------------
// out[m][n] = relu( sum_k A[m][k] * W[n][k] + bias[n] ),  K = 256
// A = [agg | feat], bf16 hi/lo split, 3 MMAs per fragment pair.
// mode 0: write feat hi/lo + f16 for next layer.
// mode 1: reduce rows against Wl2/Wr2 -> g_s, g_z (layer-2 scalarization).
#define SM_BH 0
#define SM_BL 67584
#define SM_AB 135168
#define SM_RED 208896
#define SMEM_TOTAL 210944
#define ABUF_HALF 18432   // bf16 elements per A buffer (hi 9216 + lo 9216)

__device__ __forceinline__ unsigned su32(const void* p) {
    return (unsigned)__cvta_generic_to_shared(p);
}
__device__ __forceinline__ void cpa16(unsigned dst, const void* src, bool ok) {
    asm volatile("cp.async.cg.shared.global [%0], [%1], 16, %2;"
                 :: "r"(dst), "l"(src), "r"(ok ? 16 : 0));
}
__device__ __forceinline__ void mma_bf16(float* d, const unsigned* a,
                                         unsigned b0, unsigned b1) {
    asm volatile(
        "mma.sync.aligned.m16n8k16.row.col.f32.bf16.bf16.f32 "
        "{%0,%1,%2,%3}, {%4,%5,%6,%7}, {%8,%9}, {%0,%1,%2,%3};"
        : "+f"(d[0]), "+f"(d[1]), "+f"(d[2]), "+f"(d[3])
        : "r"(a[0]), "r"(a[1]), "r"(a[2]), "r"(a[3]), "r"(b0), "r"(b1));
}

__global__ __launch_bounds__(512) void gemm_mma(
    const __nv_bfloat16* __restrict__ aggHi, const __nv_bfloat16* __restrict__ aggLo,
    const __nv_bfloat16* __restrict__ featHi, const __nv_bfloat16* __restrict__ featLo,
    const float* __restrict__ bias,
    __nv_bfloat16* __restrict__ outHi, __nv_bfloat16* __restrict__ outLo,
    __half* __restrict__ outF16,
    const float* __restrict__ Wl2, const float* __restrict__ Wr2,
    int n, int mode)
{
    extern __shared__ char sm[];
    __nv_bfloat16* Bh = (__nv_bfloat16*)(sm + SM_BH);   // [128][264]
    __nv_bfloat16* Bl = (__nv_bfloat16*)(sm + SM_BL);   // [128][264]
    __nv_bfloat16* Ab = (__nv_bfloat16*)(sm + SM_AB);   // 2 x (hi[128][72], lo[128][72])
    float* sS   = (float*)(sm + SM_RED);                // [128]
    float* sZ   = sS + 128;
    float* sWl2 = sZ + 128;                             // [128]
    float* sWr2 = sWl2 + 128;

    int tid = threadIdx.x;
    int lane = tid & 31;
    int wid = tid >> 5;
    int mwarp = wid & 7;          // 8 m-slots of 16 rows
    int nwarp = wid >> 3;         // 2 n-halves of 64 cols
    int g = lane >> 2, t = lane & 3;

    if (tid < 128) {
        sS[tid] = 0.f;
        sZ[tid] = 0.f;
        if (mode == 1) { sWl2[tid] = Wl2[tid]; sWr2[tid] = Wr2[tid]; }
    }

    // --- load B (weights hi/lo) into smem ---
    for (int u = tid; u < 4096; u += 512) {
        int nrow = u >> 5, seg = u & 31;
        cpa16(su32(Bh + nrow * 264) + seg * 16, g_whi + nrow * 256 + seg * 8, true);
        cpa16(su32(Bl + nrow * 264) + seg * 16, g_wlo + nrow * 256 + seg * 8, true);
    }

    // --- A chunk loader: chunk c covers k [c*64, c*64+64) ---
    auto loadA = [&](int c, int buf) {
        const __nv_bfloat16* sH = (c < 2) ? aggHi : featHi;
        const __nv_bfloat16* sL = (c < 2) ? aggLo : featLo;
        int koff = (c & 1) * 64;
        __nv_bfloat16* dH = Ab + buf * ABUF_HALF;
        __nv_bfloat16* dL = dH + 9216;
        #pragma unroll
        for (int u = tid; u < 1024; u += 512) {
            int r = u >> 3, seg = u & 7;
            int row = blockIdx.x * 128 + r;
            bool ok = row < n;
            int rr = ok ? row : 0;
            cpa16(su32(dH + r * 72) + seg * 16,
                  sH + (size_t)rr * 128 + koff + seg * 8, ok);
            cpa16(su32(dL + r * 72) + seg * 16,
                  sL + (size_t)rr * 128 + koff + seg * 8, ok);
        }
    };

    loadA(0, 0);
    asm volatile("cp.async.commit_group;");
    loadA(1, 1);
    asm volatile("cp.async.commit_group;");
    asm volatile("cp.async.wait_group 1;");
    __syncthreads();

    float acc[8][4];
    #pragma unroll
    for (int i = 0; i < 8; ++i)
        #pragma unroll
        for (int j = 0; j < 4; ++j) acc[i][j] = 0.f;

    for (int c = 0; c < 4; ++c) {
        const __nv_bfloat16* Ah = Ab + (c & 1) * ABUF_HALF;
        const __nv_bfloat16* Al = Ah + 9216;
        #pragma unroll
        for (int ks = 0; ks < 4; ++ks) {
            int k = ks * 16;
            const __nv_bfloat16* pa = Ah + (mwarp * 16 + g) * 72 + t * 2 + k;
            const __nv_bfloat16* pl = Al + (mwarp * 16 + g) * 72 + t * 2 + k;
            unsigned ah[4], al[4];
            ah[0] = *(const unsigned*)(pa);
            ah[1] = *(const unsigned*)(pa + 8 * 72);
            ah[2] = *(const unsigned*)(pa + 8);
            ah[3] = *(const unsigned*)(pa + 8 * 72 + 8);
            al[0] = *(const unsigned*)(pl);
            al[1] = *(const unsigned*)(pl + 8 * 72);
            al[2] = *(const unsigned*)(pl + 8);
            al[3] = *(const unsigned*)(pl + 8 * 72 + 8);
            #pragma unroll
            for (int nt = 0; nt < 8; ++nt) {
                int nn = nwarp * 64 + nt * 8 + g;
                int kk = c * 64 + k + t * 2;
                unsigned b0h = *(const unsigned*)(Bh + nn * 264 + kk);
                unsigned b1h = *(const unsigned*)(Bh + nn * 264 + kk + 8);
                unsigned b0l = *(const unsigned*)(Bl + nn * 264 + kk);
                unsigned b1l = *(const unsigned*)(Bl + nn * 264 + kk + 8);
                mma_bf16(acc[nt], ah, b0h, b1h);
                mma_bf16(acc[nt], ah, b0l, b1l);
                mma_bf16(acc[nt], al, b0h, b1h);
            }
        }
        __syncthreads();
        if (c + 2 < 4) loadA(c + 2, c & 1);
        asm volatile("cp.async.commit_group;");
        asm volatile("cp.async.wait_group 1;");
        __syncthreads();
    }

    // --- epilogue ---
    int row0 = blockIdx.x * 128 + mwarp * 16 + g;
    int row1 = row0 + 8;
    float ps0 = 0.f, pz0 = 0.f, ps1 = 0.f, pz1 = 0.f;
    #pragma unroll
    for (int nt = 0; nt < 8; ++nt) {
        int col = nwarp * 64 + nt * 8 + t * 2;
        float b0 = __ldg(bias + col), b1 = __ldg(bias + col + 1);
        float v0 = fmaxf(acc[nt][0] + b0, 0.f);
        float v1 = fmaxf(acc[nt][1] + b1, 0.f);
        float v2 = fmaxf(acc[nt][2] + b0, 0.f);
        float v3 = fmaxf(acc[nt][3] + b1, 0.f);
        if (mode == 0) {
            if (row0 < n) {
                unsigned h01, l01;
                split2(v0, v1, h01, l01);
                *((unsigned*)(outHi + (size_t)row0 * D + col)) = h01;
                *((unsigned*)(outLo + (size_t)row0 * D + col)) = l01;
                __half2 f = __floats2half2_rn(v0, v1);
                *((unsigned*)(outF16 + (size_t)row0 * D + col)) = *(unsigned*)&f;
            }
            if (row1 < n) {
                unsigned h23, l23;
                split2(v2, v3, h23, l23);
                *((unsigned*)(outHi + (size_t)row1 * D + col)) = h23;
                *((unsigned*)(outLo + (size_t)row1 * D + col)) = l23;
                __half2 f = __floats2half2_rn(v2, v3);
                *((unsigned*)(outF16 + (size_t)row1 * D + col)) = *(unsigned*)&f;
            }
        } else {
            float wl0 = sWl2[col], wl1 = sWl2[col + 1];
            float wr0 = sWr2[col], wr1 = sWr2[col + 1];
            ps0 += v0 * wl0 + v1 * wl1;
            pz0 += v0 * wr0 + v1 * wr1;
            ps1 += v2 * wl0 + v3 * wl1;
            pz1 += v2 * wr0 + v3 * wr1;
        }
    }
    if (mode == 1) {
        #pragma unroll
        for (int m = 1; m <= 2; m <<= 1) {
            ps0 += __shfl_xor_sync(0xffffffffu, ps0, m);
            pz0 += __shfl_xor_sync(0xffffffffu, pz0, m);
            ps1 += __shfl_xor_sync(0xffffffffu, ps1, m);
            pz1 += __shfl_xor_sync(0xffffffffu, pz1, m);
        }
        if (t == 0) {
            if (row0 < n) {
                atomicAdd(&sS[mwarp * 16 + g], ps0);
                atomicAdd(&sZ[mwarp * 16 + g], pz0);
            }
            if (row1 < n) {
                atomicAdd(&sS[mwarp * 16 + g + 8], ps1);
                atomicAdd(&sZ[mwarp * 16 + g + 8], pz1);
            }
        }
        __syncthreads();
        if (tid < 128) {
            int row = blockIdx.x * 128 + tid;
            if (row < n) { g_s[row] = sS[tid]; g_z[row] = sZ[tid]; }
        }
    }
}

// ---------------- final: mean-gather scalar + bias + sigmoid ----------------
__global__ void final_fused(const float* __restrict__ bl2,
                            float* __restrict__ out, int n) {
    int i = blockIdx.x * blockDim.x + threadIdx.x;
    if (i >= n) return;
    int beg = g_off[i], end = g_off[i + 1];
    float acc = 0.f;
    for (int e = beg; e < end; ++e) acc += g_s[g_csr[e]];
    float v = acc / fmaxf((float)(end - beg), 1.0f) + __ldg(bl2) + g_z[i];
    out[i] = v;
    out[n + i] = 1.0f / (1.0f + expf(-v));
}

// ---------------------------------------------------------------------------
extern "C" void kernel_launch(void* const* d_in, const int* in_sizes, int n_in,
                              void* d_out, int out_size) {
    const float* x   = (const float*)d_in[0];
    const int*   ei  = (const int*)d_in[1];
    const float* Wl0 = (const float*)d_in[2];
    const float* bl0 = (const float*)d_in[3];
    const float* Wr0 = (const float*)d_in[4];
    const float* Wl1 = (const float*)d_in[5];
    const float* bl1 = (const float*)d_in[6];
    const float* Wr1 = (const float*)d_in[7];
    const float* Wl2 = (const float*)d_in[8];
    const float* bl2 = (const float*)d_in[9];
    const float* Wr2 = (const float*)d_in[10];
    float* out = (float*)d_out;

    int n = in_sizes[0] / D;   // 100000
    int E = in_sizes[1] / 2;   // 1600000
    const int* src = ei;
    const int* dst = ei + E;

    void* p_cnt;
    cudaGetSymbolAddress(&p_cnt, g_cnt);
    __nv_bfloat16 *ahi, *alo, *fhi, *flo;
    __half* f16;
    cudaGetSymbolAddress((void**)&ahi, g_ahi);
    cudaGetSymbolAddress((void**)&alo, g_alo);
    cudaGetSymbolAddress((void**)&fhi, g_fhi);
    cudaGetSymbolAddress((void**)&flo, g_flo);
    cudaGetSymbolAddress((void**)&f16, g_f16);

    cudaFuncSetAttribute(gemm_mma, cudaFuncAttributeMaxDynamicSharedMemorySize,
                         SMEM_TOTAL);

    int gemm_blocks = (n + 127) / 128;   // 782
    int scan_blocks = (n + 1023) / 1024; // 98

    // CSR build (parallel scan)
    cudaMemsetAsync(p_cnt, 0, (size_t)n * sizeof(int));
    count_kernel<<<6250, 256>>>(dst, E);
    scan1<<<scan_blocks, 1024>>>(n);
    scan2<<<1, 128>>>(scan_blocks);
    scan3<<<scan_blocks, 1024>>>(n, E);
    fill_kernel<<<6250, 256>>>(src, dst, E);

    // Layer 0
    convert_x<<<(n * 32 + 255) / 256, 256>>>(x, n * 32);
    gather_mean<<<12500, 256>>>(f16, n);
    prep_w<<<128, 256>>>(Wl0, Wr0);
    gemm_mma<<<gemm_blocks, 512, SMEM_TOTAL>>>(ahi, alo, fhi, flo, bl0,
                                               fhi, flo, f16,
                                               (const float*)0, (const float*)0,
                                               n, 0);

    // Layer 1 (+ fused layer-2 scalarization: s = h2·Wl2, z = h2·Wr2)
    gather_mean<<<12500, 256>>>(f16, n);
    prep_w<<<128, 256>>>(Wl1, Wr1);
    gemm_mma<<<gemm_blocks, 512, SMEM_TOTAL>>>(ahi, alo, fhi, flo, bl1,
                                               (__nv_bfloat16*)0, (__nv_bfloat16*)0,
                                               (__half*)0, Wl2, Wr2,
                                               n, 1);

    // Layer 2 aggregation + output
    final_fused<<<(n + 255) / 256, 256>>>(bl2, out, n);
}

// round 7
// speedup vs baseline: 5.5884x; 1.7327x over previous
#include <cuda_runtime.h>
#include <cuda_fp16.h>
#include <stdint.h>
#include <math.h>

#define NN 100000
#define EE 1600000
#define D  128

// ---------------- device scratch (no allocations allowed) -------------------
__device__ __align__(16) __half g_a16[(size_t)NN * D];   // agg fp16
__device__ __align__(16) __half g_f16[(size_t)NN * D];   // feat fp16 (x -> h1)
__device__ __align__(16) __half g_w16[128 * 256];        // [Wl;Wr] fp16, [n][k]
__device__ int g_cnt[NN];
__device__ int g_pre[NN];
__device__ int g_bsum[128];
__device__ int g_off[NN + 1];
__device__ int g_cur[NN];
__device__ int g_csr[EE];
__device__ float g_s[NN];
__device__ float g_z[NN];

// ---------------- CSR build --------------------------------------------------
__global__ void count_kernel(const int* __restrict__ dst, int E) {
    int i = blockIdx.x * blockDim.x + threadIdx.x;
    int stride = gridDim.x * blockDim.x;
    for (; i < E; i += stride) atomicAdd(&g_cnt[dst[i]], 1);
}

__global__ void scan1(int n) {       // grid 98 x 1024
    __shared__ int s[1024];
    int tid = threadIdx.x;
    int i = blockIdx.x * 1024 + tid;
    int v = (i < n) ? g_cnt[i] : 0;
    s[tid] = v;
    __syncthreads();
    for (int off = 1; off < 1024; off <<= 1) {
        int t = (tid >= off) ? s[tid - off] : 0;
        __syncthreads();
        s[tid] += t;
        __syncthreads();
    }
    if (i < n) g_pre[i] = s[tid] - v;
    if (tid == 1023) g_bsum[blockIdx.x] = s[1023];
}

__global__ void scan2(int nb) {      // 1 block x 128
    __shared__ int s[128];
    int tid = threadIdx.x;
    int v = (tid < nb) ? g_bsum[tid] : 0;
    s[tid] = v;
    __syncthreads();
    for (int off = 1; off < 128; off <<= 1) {
        int t = (tid >= off) ? s[tid - off] : 0;
        __syncthreads();
        s[tid] += t;
        __syncthreads();
    }
    if (tid < nb) g_bsum[tid] = s[tid] - v;
}

__global__ void scan3(int n, int E) {
    int i = blockIdx.x * 1024 + threadIdx.x;
    if (i < n) {
        int o = g_pre[i] + g_bsum[blockIdx.x];
        g_off[i] = o;
        g_cur[i] = o;
    }
    if (i == 0) g_off[n] = E;
}

__global__ void fill_kernel(const int* __restrict__ src,
                            const int* __restrict__ dst, int E) {
    int i = blockIdx.x * blockDim.x + threadIdx.x;
    int stride = gridDim.x * blockDim.x;
    for (; i < E; i += stride) {
        int pos = atomicAdd(&g_cur[dst[i]], 1);
        g_csr[pos] = src[i];
    }
}

// ---------------- mean gather (fp16 rows, atomic-free), emits fp16 agg ------
__global__ void gather_mean(const __half* __restrict__ h, int n) {
    int lane = threadIdx.x & 31;
    int w = (blockIdx.x * blockDim.x + threadIdx.x) >> 5;
    int nw = (gridDim.x * blockDim.x) >> 5;
    for (int i = w; i < n; i += nw) {
        int beg = g_off[i], end = g_off[i + 1];
        float4 acc = make_float4(0.f, 0.f, 0.f, 0.f);
        for (int e = beg; e < end; ++e) {
            int s = g_csr[e];
            uint2 raw = __ldg(((const uint2*)(h + (size_t)s * D)) + lane);
            __half2* p = (__half2*)&raw;
            float2 f01 = __half22float2(p[0]);
            float2 f23 = __half22float2(p[1]);
            acc.x += f01.x; acc.y += f01.y; acc.z += f23.x; acc.w += f23.y;
        }
        float inv = 1.0f / fmaxf((float)(end - beg), 1.0f);
        __half2 h01 = __floats2half2_rn(acc.x * inv, acc.y * inv);
        __half2 h23 = __floats2half2_rn(acc.z * inv, acc.w * inv);
        uint2 o;
        o.x = *(unsigned*)&h01;
        o.y = *(unsigned*)&h23;
        *((uint2*)(g_a16 + (size_t)i * D + lane * 4)) = o;
    }
}

// ---------------- converters -------------------------------------------------
__global__ void convert_x(const float* __restrict__ x, int n4) {
    int i = blockIdx.x * blockDim.x + threadIdx.x;
    if (i >= n4) return;
    float4 v = __ldg(((const float4*)x) + i);
    __half2 a = __floats2half2_rn(v.x, v.y);
    __half2 b = __floats2half2_rn(v.z, v.w);
    uint2 F;
    F.x = *(unsigned*)&a;
    F.y = *(unsigned*)&b;
    *((uint2*)(g_f16 + (size_t)i * 4)) = F;
}

__global__ void prep_w(const float* __restrict__ Wl, const float* __restrict__ Wr) {
    int i = blockIdx.x * blockDim.x + threadIdx.x;  // 0..32767
    int nrow = i >> 8, k = i & 255;
    float w = (k < 128) ? Wl[nrow * 128 + k] : Wr[nrow * 128 + (k - 128)];
    g_w16[nrow * 256 + k] = __float2half_rn(w);
}

// =============================================================================
// fp16 mma.sync GEMM (persistent): out[m][n] = relu(sum_k A[m][k] W[n][k] + b)
// K=256 (A = [agg | feat] fp16). Tile: 256 rows x 128 cols, 16 warps (8m x 2n),
// each warp m32 x n64 via 16 MMAs/kstep. W resident in smem; A prefetched
// during epilogue with cp.async. ldmatrix.x4 fragment loads, 528B strides.
// =============================================================================
#define GEMM_GRID 148
#define TM 256
#define SM_B    0        // W fp16 [128][264] (67584 B)
#define SM_A    67584    // A fp16 [256][264] (135168 B)
#define SM_RED  202752   // sS[256], sZ[256], sWl2[128], sWr2[128], sB[128]
#define GEMM_SMEM 206336

__device__ __forceinline__ unsigned su32(const void* p) {
    return (unsigned)__cvta_generic_to_shared(p);
}
__device__ __forceinline__ void cpa16(unsigned dst, const void* src, bool ok) {
    asm volatile("cp.async.cg.shared.global [%0], [%1], 16, %2;"
                 :: "r"(dst), "l"(src), "r"(ok ? 16 : 0));
}
__device__ __forceinline__ void ldm4(unsigned* r, unsigned addr) {
    asm volatile("ldmatrix.sync.aligned.m8n8.x4.shared.b16 {%0,%1,%2,%3}, [%4];"
                 : "=r"(r[0]), "=r"(r[1]), "=r"(r[2]), "=r"(r[3]) : "r"(addr));
}
__device__ __forceinline__ void mma16(float* d, const unsigned* a,
                                      unsigned b0, unsigned b1) {
    asm volatile(
        "mma.sync.aligned.m16n8k16.row.col.f32.f16.f16.f32 "
        "{%0,%1,%2,%3}, {%4,%5,%6,%7}, {%8,%9}, {%0,%1,%2,%3};"
        : "+f"(d[0]), "+f"(d[1]), "+f"(d[2]), "+f"(d[3])
        : "r"(a[0]), "r"(a[1]), "r"(a[2]), "r"(a[3]), "r"(b0), "r"(b1));
}

// A tile loader: 256 rows x 256 fp16 (row = [agg row | feat row]), 528B stride
__device__ __forceinline__ void loadA16(unsigned smb, int tid, int n, int tile,
                                        const __half* agg, const __half* feat) {
    #pragma unroll
    for (int u = tid; u < 8192; u += 512) {
        int r = u >> 5, seg = u & 31;
        int row = tile * TM + r;
        bool ok = row < n;
        const __half* srcb = (seg < 16) ? agg : feat;
        size_t off = (size_t)(ok ? row : 0) * 128 + (seg & 15) * 8;
        cpa16(smb + SM_A + r * 528 + seg * 16, srcb + off, ok);
    }
}

__global__ __launch_bounds__(512, 1) void gemm16(
    const __half* __restrict__ agg, const __half* __restrict__ feat,
    const float* __restrict__ bias,
    __half* __restrict__ outF16,
    const float* __restrict__ Wl2, const float* __restrict__ Wr2,
    int n, int mode)
{
    extern __shared__ char sm[];
    unsigned smb = su32(sm);
    float* sS   = (float*)(sm + SM_RED);   // [256]
    float* sZ   = sS + 256;                // [256]
    float* sWl2 = sZ + 256;                // [128]
    float* sWr2 = sWl2 + 128;              // [128]
    float* sB   = sWr2 + 128;              // [128]

    int tid = threadIdx.x;
    int lane = tid & 31;
    int wid = tid >> 5;
    int mwarp = wid & 7;          // rows [mwarp*32, +32)
    int nwarp = wid >> 3;         // cols [nwarp*64, +64)
    int ntiles = (n + TM - 1) / TM;

    if (tid < 128) {
        sB[tid] = bias[tid];
        if (mode == 1) { sWl2[tid] = Wl2[tid]; sWr2[tid] = Wr2[tid]; }
    }

    // W resident load
    #pragma unroll
    for (int u = tid; u < 4096; u += 512) {
        int nrow = u >> 5, kc = u & 31;
        cpa16(smb + SM_B + nrow * 528 + kc * 16, g_w16 + nrow * 256 + kc * 8, true);
    }
    int t0 = blockIdx.x;
    if (t0 < ntiles) loadA16(smb, tid, n, t0, agg, feat);
    asm volatile("cp.async.commit_group;");

    // ldmatrix per-thread addresses
    // A tiles order: (m0-7,k0-7),(m8-15,k0-7),(m0-7,k8-15),(m8-15,k8-15)
    unsigned aAddr = smb + SM_A
        + (mwarp * 32 + (lane & 7) + ((lane >> 3) & 1) * 8) * 528
        + ((lane >> 4) & 1) * 16;
    // B tiles order: (n0-7,k0-7),(n0-7,k8-15),(n8-15,k0-7),(n8-15,k8-15)
    unsigned bAddr = smb + SM_B
        + (nwarp * 64 + (lane & 7) + ((lane >> 4) & 1) * 8) * 528
        + ((lane >> 3) & 1) * 16;

    int g = lane >> 2, tq = lane & 3;

    for (int t = t0; t < ntiles; t += gridDim.x) {
        if (mode == 1 && tid < 256) { sS[tid] = 0.f; sZ[tid] = 0.f; }

        asm volatile("cp.async.wait_group 0;");
        __syncthreads();

        float acc[2][8][4];
        #pragma unroll
        for (int h = 0; h < 2; ++h)
            #pragma unroll
            for (int i = 0; i < 8; ++i)
                #pragma unroll
                for (int j = 0; j < 4; ++j) acc[h][i][j] = 0.f;

        #pragma unroll
        for (int k = 0; k < 16; ++k) {
            unsigned a0[4], a1[4], b[4];
            ldm4(a0, aAddr + k * 32);
            ldm4(a1, aAddr + 16 * 528 + k * 32);
            #pragma unroll
            for (int p = 0; p < 4; ++p) {
                ldm4(b, bAddr + p * 16 * 528 + k * 32);
                mma16(acc[0][2 * p],     a0, b[0], b[1]);
                mma16(acc[0][2 * p + 1], a0, b[2], b[3]);
                mma16(acc[1][2 * p],     a1, b[0], b[1]);
                mma16(acc[1][2 * p + 1], a1, b[2], b[3]);
            }
        }
        __syncthreads();           // all warps done reading A smem

        int tn = t + gridDim.x;    // prefetch next tile during epilogue
        if (tn < ntiles) loadA16(smb, tid, n, tn, agg, feat);
        asm volatile("cp.async.commit_group;");

        // ---- epilogue ----
        #pragma unroll
        for (int h = 0; h < 2; ++h) {
            int r0 = t * TM + mwarp * 32 + h * 16 + g;
            int r1 = r0 + 8;
            float ps0 = 0.f, pz0 = 0.f, ps1 = 0.f, pz1 = 0.f;
            #pragma unroll
            for (int nt = 0; nt < 8; ++nt) {
                int col = nwarp * 64 + nt * 8 + tq * 2;
                float b0 = sB[col], b1 = sB[col + 1];
                float v0 = fmaxf(acc[h][nt][0] + b0, 0.f);
                float v1 = fmaxf(acc[h][nt][1] + b1, 0.f);
                float v2 = fmaxf(acc[h][nt][2] + b0, 0.f);
                float v3 = fmaxf(acc[h][nt][3] + b1, 0.f);
                if (mode == 0) {
                    if (r0 < n) {
                        __half2 f = __floats2half2_rn(v0, v1);
                        *((unsigned*)(outF16 + (size_t)r0 * D + col)) = *(unsigned*)&f;
                    }
                    if (r1 < n) {
                        __half2 f = __floats2half2_rn(v2, v3);
                        *((unsigned*)(outF16 + (size_t)r1 * D + col)) = *(unsigned*)&f;
                    }
                } else {
                    float wl0 = sWl2[col], wl1 = sWl2[col + 1];
                    float wr0 = sWr2[col], wr1 = sWr2[col + 1];
                    ps0 += v0 * wl0 + v1 * wl1;
                    pz0 += v0 * wr0 + v1 * wr1;
                    ps1 += v2 * wl0 + v3 * wl1;
                    pz1 += v2 * wr0 + v3 * wr1;
                }
            }
            if (mode == 1) {
                #pragma unroll
                for (int m = 1; m <= 2; m <<= 1) {
                    ps0 += __shfl_xor_sync(0xffffffffu, ps0, m);
                    pz0 += __shfl_xor_sync(0xffffffffu, pz0, m);
                    ps1 += __shfl_xor_sync(0xffffffffu, ps1, m);
                    pz1 += __shfl_xor_sync(0xffffffffu, pz1, m);
                }
                if (tq == 0) {
                    int lr = mwarp * 32 + h * 16 + g;
                    atomicAdd(&sS[lr], ps0);
                    atomicAdd(&sZ[lr], pz0);
                    atomicAdd(&sS[lr + 8], ps1);
                    atomicAdd(&sZ[lr + 8], pz1);
                }
            }
        }
        if (mode == 1) {
            __syncthreads();
            if (tid < 256) {
                int row = t * TM + tid;
                if (row < n) { g_s[row] = sS[tid]; g_z[row] = sZ[tid]; }
            }
        }
    }
}

// ---------------- final: mean-gather scalar + bias + sigmoid ----------------
__global__ void final_fused(const float* __restrict__ bl2,
                            float* __restrict__ out, int n) {
    int i = blockIdx.x * blockDim.x + threadIdx.x;
    if (i >= n) return;
    int beg = g_off[i], end = g_off[i + 1];
    float acc = 0.f;
    for (int e = beg; e < end; ++e) acc += g_s[g_csr[e]];
    float v = acc / fmaxf((float)(end - beg), 1.0f) + __ldg(bl2) + g_z[i];
    out[i] = v;
    out[n + i] = 1.0f / (1.0f + expf(-v));
}

// ---------------------------------------------------------------------------
extern "C" void kernel_launch(void* const* d_in, const int* in_sizes, int n_in,
                              void* d_out, int out_size) {
    const float* x   = (const float*)d_in[0];
    const int*   ei  = (const int*)d_in[1];
    const float* Wl0 = (const float*)d_in[2];
    const float* bl0 = (const float*)d_in[3];
    const float* Wr0 = (const float*)d_in[4];
    const float* Wl1 = (const float*)d_in[5];
    const float* bl1 = (const float*)d_in[6];
    const float* Wr1 = (const float*)d_in[7];
    const float* Wl2 = (const float*)d_in[8];
    const float* bl2 = (const float*)d_in[9];
    const float* Wr2 = (const float*)d_in[10];
    float* out = (float*)d_out;

    int n = in_sizes[0] / D;   // 100000
    int E = in_sizes[1] / 2;   // 1600000
    const int* src = ei;
    const int* dst = ei + E;

    void* p_cnt;
    cudaGetSymbolAddress(&p_cnt, g_cnt);
    __half *a16, *f16;
    cudaGetSymbolAddress((void**)&a16, g_a16);
    cudaGetSymbolAddress((void**)&f16, g_f16);

    cudaFuncSetAttribute(gemm16, cudaFuncAttributeMaxDynamicSharedMemorySize,
                         GEMM_SMEM);

    int scan_blocks = (n + 1023) / 1024; // 98

    // CSR build (parallel scan)
    cudaMemsetAsync(p_cnt, 0, (size_t)n * sizeof(int));
    count_kernel<<<6250, 256>>>(dst, E);
    scan1<<<scan_blocks, 1024>>>(n);
    scan2<<<1, 128>>>(scan_blocks);
    scan3<<<scan_blocks, 1024>>>(n, E);
    fill_kernel<<<6250, 256>>>(src, dst, E);

    // Layer 0
    convert_x<<<(n * 32 + 255) / 256, 256>>>(x, n * 32);
    gather_mean<<<12500, 256>>>(f16, n);
    prep_w<<<128, 256>>>(Wl0, Wr0);
    gemm16<<<GEMM_GRID, 512, GEMM_SMEM>>>(a16, f16, bl0, f16,
                                          (const float*)0, (const float*)0,
                                          n, 0);

    // Layer 1 (+ fused layer-2 scalarization: s = h2·Wl2, z = h2·Wr2)
    gather_mean<<<12500, 256>>>(f16, n);
    prep_w<<<128, 256>>>(Wl1, Wr1);
    gemm16<<<GEMM_GRID, 512, GEMM_SMEM>>>(a16, f16, bl1, (__half*)0,
                                          Wl2, Wr2, n, 1);

    // Layer 2 aggregation + output
    final_fused<<<(n + 255) / 256, 256>>>(bl2, out, n);
}